// round 16
// baseline (speedup 1.0000x reference)
#include <cuda_runtime.h>
#include <cstdint>

#define NTOK 25
#define DIM  128
#define NH   4
#define NWIN 64
#define WSQ  49

typedef unsigned long long u64t;

// fp16 weight fragments, B-frag order.
// float4 = 4 b32 words: {b0(step 2*s2), b1(step 2*s2), b0(step 2*s2+1), b1(step 2*s2+1)}
__device__ float4 g_bqkv16[48 * 4 * 32];   // [nt(48)][s2(4)][lane(32)]
__device__ float4 g_bproj16[16 * 4 * 32];  // [nt(16)][s2(4)][lane(32)]
// Precomputed bias+mask: [w][h][m][n]  (n innermost for coalesced lane reads)
__device__ float g_bm[NWIN * NH * NTOK * NTOK];

// pack two fp32 -> f16x2 (lo in low half)
__device__ __forceinline__ uint32_t f2h2(float lo, float hi) {
    uint32_t u;
    asm("cvt.rn.f16x2.f32 %0, %1, %2;" : "=r"(u) : "f"(hi), "f"(lo));
    return u;
}

// Single merged prologue: fp16 weight fragment packing + bias/mask table.
__global__ void prologue(const float* __restrict__ qkv_w,
                         const float* __restrict__ proj_w,
                         const float* __restrict__ mask,
                         const int*   __restrict__ ids_keep,
                         const float* __restrict__ bias_table,
                         const int*   __restrict__ rel_index)
{
    const int idx = blockIdx.x * 256 + threadIdx.x;
    if (idx < 8192) {
        const int p = idx;
        const int l = p & 31;
        const int s2 = (p >> 5) & 3;
        const float* wsrc;
        float4* dst;
        int nt;
        if (p < 48 * 4 * 32) { nt = p >> 7; wsrc = qkv_w;  dst = &g_bqkv16[p]; }
        else { const int q = p - 48 * 4 * 32; nt = q >> 7; wsrc = proj_w; dst = &g_bproj16[q]; }
        const int n = nt * 8 + (l >> 2);
        const int k = s2 * 32 + 2 * (l & 3);
        const float* wr = wsrc + n * DIM + k;
        float4 o;
        ((uint32_t*)&o)[0] = f2h2(wr[0],  wr[1]);    // step 2*s2,   b0
        ((uint32_t*)&o)[1] = f2h2(wr[8],  wr[9]);    // step 2*s2,   b1
        ((uint32_t*)&o)[2] = f2h2(wr[16], wr[17]);   // step 2*s2+1, b0
        ((uint32_t*)&o)[3] = f2h2(wr[24], wr[25]);   // step 2*s2+1, b1
        *dst = o;
    } else {
        const int j = idx - 8192;
        if (j < NWIN * NH * NTOK * NTOK) {
            const int w = j / (NH * NTOK * NTOK);
            const int rem = j - w * (NH * NTOK * NTOK);
            const int h = rem / (NTOK * NTOK);
            const int r2 = rem - h * (NTOK * NTOK);
            const int m = r2 / NTOK, n = r2 - m * NTOK;
            const int in_ = ids_keep[w * NTOK + n];
            const int im  = ids_keep[w * NTOK + m];
            g_bm[j] = bias_table[rel_index[in_ * WSQ + im] * NH + h]
                    + mask[(w * WSQ + in_) * WSQ + im];
        }
    }
}

#define MMA_F16(Cv, Av, b0, b1)                                        \
    asm("mma.sync.aligned.m16n8k16.row.col.f32.f16.f16.f32 "           \
        "{%0,%1,%2,%3}, {%4,%5,%6,%7}, {%8,%9}, {%0,%1,%2,%3};"        \
        : "+f"(Cv[0]), "+f"(Cv[1]), "+f"(Cv[2]), "+f"(Cv[3])           \
        : "r"(Av[0]), "r"(Av[1]), "r"(Av[2]), "r"(Av[3]), "r"(b0), "r"(b1))

__device__ __forceinline__ u64t pack2(float lo, float hi) {
    u64t r; asm("mov.b64 %0, {%1, %2};" : "=l"(r) : "f"(lo), "f"(hi)); return r;
}
__device__ __forceinline__ float2 unpack2(u64t v) {
    float2 r; asm("mov.b64 {%0, %1}, %2;" : "=f"(r.x), "=f"(r.y) : "l"(v)); return r;
}
#define FMA2(d, a, b, c) \
    asm("fma.rn.f32x2 %0, %1, %2, %3;" : "=l"(d) : "l"(a), "l"(b), "l"(c))
#define ADD2(d, a, b) \
    asm("add.rn.f32x2 %0, %1, %2;" : "=l"(d) : "l"(a), "l"(b))
#define MUL2(d, a, b) \
    asm("mul.rn.f32x2 %0, %1, %2;" : "=l"(d) : "l"(a), "l"(b))

// fp16 A-frag word address (32-bit word index). chunk in [0,16): mt*8 + step.
// Swizzle low 3 bits of chunk by (l>>2)&7; keep mt bit. Each lane holds 4 words (16B).
__device__ __forceinline__ int af_addr16(int chunk, int l, int e) {
    return ((((chunk) & 8) | (((chunk) ^ ((l) >> 2)) & 7)) * 32 + (l)) * 4 + (e);
}

// Shared layout (floats):
//   af   [0, 2048)           x / O A-frags fp16 (16 chunks x 32 lanes x 4 words)
//   qs   [2048, 7168)        q swizzled fp32: [h][row32][40], chunk-XOR by row
//   ks   [7168, 11776)       [h][row32][36] fp32 (rows 25-31 pad, never read)
//   vs   [11776, 16384)      [h][row32][36] fp32 (also P0 staging: 25 x 136 = 3400)
#define OFF_Q  2048
#define OFF_K  7168
#define OFF_V  11776
#define SM_FLOATS 16384

__global__ __launch_bounds__(256, 2)
void win_attn_kernel(const float* __restrict__ x,
                     const float* __restrict__ qkv_b,
                     const float* __restrict__ proj_b,
                     float* __restrict__ out)
{
    extern __shared__ float sm[];
    uint32_t* uaf = (uint32_t*)sm;
    float* qs = sm + OFF_Q;
    float* ks = sm + OFF_K;
    float* vs = sm + OFF_V;
    float* xstg = vs;            // P0 staging, consumed before P1 writes vs

    const int b = blockIdx.x;
    const int w = b & (NWIN - 1);
    const int t = threadIdx.x;
    const int wid = t >> 5, lane = t & 31;
    const int g = lane >> 2, qd = lane & 3;

    // ---- P0a: coalesced load x -> linear staging [row][136] ----
    {
        const float4* xb4 = (const float4*)(x + (size_t)b * (NTOK * DIM));
        #pragma unroll
        for (int i = 0; i < 3; i++) {
            const int e4 = t + 256 * i;
            const int row = e4 >> 5, col4 = e4 & 31;
            *(float4*)(xstg + row * 136 + col4 * 4) = xb4[e4];
        }
        if (t < 32) {
            const int e4 = 768 + t;
            const int row = e4 >> 5, col4 = e4 & 31;
            *(float4*)(xstg + row * 136 + col4 * 4) = xb4[e4];
        }
    }
    __syncthreads();

    // ---- P0b: pack staging -> fp16 A-frag layout (swizzled), rows >= 25 zeroed ----
    #pragma unroll
    for (int i = 0; i < 2; i++) {
        const int pos = t + 256 * i;              // 512 positions
        const int l = pos & 31, chunk = pos >> 5;
        const int mt = chunk >> 3, step = chunk & 7;
        const int r0 = mt * 16 + (l >> 2);
        const int r1 = r0 + 8;
        const int k0 = step * 16 + 2 * (l & 3);
        const float2 xa = *(const float2*)(xstg + r0 * 136 + k0);
        const float2 xc = *(const float2*)(xstg + r0 * 136 + k0 + 8);
        float2 xb = make_float2(0.f, 0.f), xd = make_float2(0.f, 0.f);
        if (r1 < NTOK) {
            xb = *(const float2*)(xstg + r1 * 136 + k0);
            xd = *(const float2*)(xstg + r1 * 136 + k0 + 8);
        }
        uint4 o;
        o.x = f2h2(xa.x, xa.y);   // a0: (r0, k0..k0+1)
        o.y = f2h2(xb.x, xb.y);   // a1: (r1, k0..k0+1)
        o.z = f2h2(xc.x, xc.y);   // a2: (r0, k0+8..k0+9)
        o.w = f2h2(xd.x, xd.y);   // a3: (r1, k0+8..k0+9)
        *(uint4*)(uaf + af_addr16(chunk, l, 0)) = o;
    }
    __syncthreads();

    // ---- P1: QKV via fp16 mma (m16n8k16). Warp owns 48 cols (6 ntiles) ----
    {
        float C[6][2][4];
        #pragma unroll
        for (int nt = 0; nt < 6; nt++) {
            const int j0 = (wid * 6 + nt) * 8 + qd * 2;
            const float2 bb = *(const float2*)(qkv_b + j0);
            #pragma unroll
            for (int mt = 0; mt < 2; mt++) {
                C[nt][mt][0] = bb.x; C[nt][mt][1] = bb.y;
                C[nt][mt][2] = bb.x; C[nt][mt][3] = bb.y;
            }
        }
        #pragma unroll
        for (int s2 = 0; s2 < 4; s2++) {
            uint32_t A[2][2][4];   // [mt][ss]
            #pragma unroll
            for (int mt = 0; mt < 2; mt++)
                #pragma unroll
                for (int ss = 0; ss < 2; ss++) {
                    const uint4 av = *(const uint4*)(uaf + af_addr16(mt * 8 + s2 * 2 + ss, lane, 0));
                    A[mt][ss][0] = av.x; A[mt][ss][1] = av.y;
                    A[mt][ss][2] = av.z; A[mt][ss][3] = av.w;
                }
            #pragma unroll
            for (int nt = 0; nt < 6; nt++) {
                const float4 bv = g_bqkv16[((wid * 6 + nt) * 4 + s2) * 32 + lane];
                const uint32_t b0 = ((const uint32_t*)&bv)[0], b1 = ((const uint32_t*)&bv)[1];
                const uint32_t b2 = ((const uint32_t*)&bv)[2], b3 = ((const uint32_t*)&bv)[3];
                MMA_F16(C[nt][0], A[0][0], b0, b1);
                MMA_F16(C[nt][1], A[1][0], b0, b1);
                MMA_F16(C[nt][0], A[0][1], b2, b3);
                MMA_F16(C[nt][1], A[1][1], b2, b3);
            }
        }
        const float scaleq = 0.17677669529663687f;
        #pragma unroll
        for (int nt = 0; nt < 6; nt++) {
            const int j0 = (wid * 6 + nt) * 8 + qd * 2;
            const int part = j0 >> 7, h = (j0 >> 5) & 3, d0 = j0 & 31;
            if (part == 0) {
                #pragma unroll
                for (int mt = 0; mt < 2; mt++) {
                    const int row = mt * 16 + g;
                    const int phys = (d0 >> 2) ^ ((row >> 2) & 7);
                    *(float2*)(qs + h * 1280 + row * 40 + phys * 4 + (d0 & 3)) =
                        make_float2(C[nt][mt][0] * scaleq, C[nt][mt][1] * scaleq);
                    const int row2 = row + 8;
                    if (row2 < NTOK) {
                        const int phys2 = (d0 >> 2) ^ ((row2 >> 2) & 7);
                        *(float2*)(qs + h * 1280 + row2 * 40 + phys2 * 4 + (d0 & 3)) =
                            make_float2(C[nt][mt][2] * scaleq, C[nt][mt][3] * scaleq);
                    }
                }
            } else {
                // ks/vs padded to 32 rows: store both row and row+8 unguarded
                float* base = (part == 1 ? ks : vs) + h * 1152 + d0;
                #pragma unroll
                for (int mt = 0; mt < 2; mt++) {
                    const int row = mt * 16 + g;
                    *(float2*)(base + row * 36) = make_float2(C[nt][mt][0], C[nt][mt][1]);
                    *(float2*)(base + (row + 8) * 36) = make_float2(C[nt][mt][2], C[nt][mt][3]);
                }
            }
        }
    }
    __syncthreads();

    // ---- P2: attention (warps 0-3; warp=head, lane=token). Output -> af (fp16) ----
    if (t < 128) {
        const int h = wid, n = lane;
        if (n < NTOK) {
            float r[NTOK];
            const float* bmb = g_bm + ((w * NH + h) * NTOK) * NTOK + n;
            {   // scores: q (swizzled regs) dot k; bias folded into accumulator init
                ulonglong2 q8[8];
                const int swz = (n >> 2) & 7;
                const float* qb = qs + h * 1280 + n * 40;
                #pragma unroll
                for (int p = 0; p < 8; p++)
                    q8[p] = *(const ulonglong2*)(qb + (p ^ swz) * 4);
                float bm_next = bmb[0];
                #pragma unroll
                for (int m = 0; m < NTOK; m++) {
                    const float bm = bm_next;
                    if (m + 1 < NTOK) bm_next = bmb[(m + 1) * NTOK];
                    const ulonglong2* kr = (const ulonglong2*)(ks + h * 1152 + m * 36);
                    u64t a0 = pack2(bm, 0.f), a1 = 0, a2 = 0, a3 = 0;
                    #pragma unroll
                    for (int p = 0; p < 8; p += 2) {
                        const ulonglong2 kv0 = kr[p];
                        FMA2(a0, q8[p].x, kv0.x, a0);
                        FMA2(a1, q8[p].y, kv0.y, a1);
                        const ulonglong2 kv1 = kr[p + 1];
                        FMA2(a2, q8[p + 1].x, kv1.x, a2);
                        FMA2(a3, q8[p + 1].y, kv1.y, a3);
                    }
                    ADD2(a0, a0, a2);
                    ADD2(a1, a1, a3);
                    ADD2(a0, a0, a1);
                    const float2 u = unpack2(a0);
                    r[m] = u.x + u.y;
                }
            }
            // softmax without max-subtraction (scores bounded ~|6| by construction)
            float s = 0.f;
            #pragma unroll
            for (int m = 0; m < NTOK; m++) { r[m] = __expf(r[m]); s += r[m]; }
            const float inv = 1.0f / s;
            const u64t inv2 = pack2(inv, inv);
            // AV in two 16-wide halves; scale once by inv; store half2 to af
            const int mt = n >> 4, rr = n & 15;
            const int lane_base = (rr & 7) * 4;
            const int regbase = (rr >= 8) ? 1 : 0;
            #pragma unroll
            for (int half = 0; half < 2; half++) {
                u64t o2[8];
                #pragma unroll
                for (int p = 0; p < 8; p++) o2[p] = 0;
                #pragma unroll
                for (int m = 0; m < NTOK; m++) {
                    const ulonglong2* vr =
                        (const ulonglong2*)(vs + h * 1152 + m * 36 + half * 16);
                    const u64t pm = pack2(r[m], r[m]);
                    #pragma unroll
                    for (int p = 0; p < 4; p++) {
                        const ulonglong2 vv = vr[p];
                        FMA2(o2[2 * p],     vv.x, pm, o2[2 * p]);
                        FMA2(o2[2 * p + 1], vv.y, pm, o2[2 * p + 1]);
                    }
                }
                const int cs = 2 * h + half;       // chunk step for cols [32h+16*half, +16)
                #pragma unroll
                for (int j = 0; j < 8; j++) {      // cols kk = 2j, 2j+1 within the chunk
                    MUL2(o2[j], o2[j], inv2);
                    const float2 u = unpack2(o2[j]);
                    const int reg = regbase + ((j >= 4) ? 2 : 0);
                    const int l_ = lane_base + (j & 3);
                    uaf[af_addr16(mt * 8 + cs, l_, reg)] = f2h2(u.x, u.y);
                }
            }
        }
    }
    __syncthreads();

    // ---- P3: proj via fp16 mma. Warp owns 16 cols (2 ntiles) ----
    {
        float C[2][2][4];
        #pragma unroll
        for (int nt2 = 0; nt2 < 2; nt2++) {
            const int j0 = (wid * 2 + nt2) * 8 + qd * 2;
            const float2 bb = *(const float2*)(proj_b + j0);
            #pragma unroll
            for (int mt = 0; mt < 2; mt++) {
                C[nt2][mt][0] = bb.x; C[nt2][mt][1] = bb.y;
                C[nt2][mt][2] = bb.x; C[nt2][mt][3] = bb.y;
            }
        }
        #pragma unroll
        for (int s2 = 0; s2 < 4; s2++) {
            uint32_t A[2][2][4];
            #pragma unroll
            for (int mt = 0; mt < 2; mt++)
                #pragma unroll
                for (int ss = 0; ss < 2; ss++) {
                    const uint4 av = *(const uint4*)(uaf + af_addr16(mt * 8 + s2 * 2 + ss, lane, 0));
                    A[mt][ss][0] = av.x; A[mt][ss][1] = av.y;
                    A[mt][ss][2] = av.z; A[mt][ss][3] = av.w;
                }
            #pragma unroll
            for (int nt2 = 0; nt2 < 2; nt2++) {
                const float4 bv = g_bproj16[((wid * 2 + nt2) * 4 + s2) * 32 + lane];
                const uint32_t b0 = ((const uint32_t*)&bv)[0], b1 = ((const uint32_t*)&bv)[1];
                const uint32_t b2 = ((const uint32_t*)&bv)[2], b3 = ((const uint32_t*)&bv)[3];
                MMA_F16(C[nt2][0], A[0][0], b0, b1);
                MMA_F16(C[nt2][1], A[1][0], b0, b1);
                MMA_F16(C[nt2][0], A[0][1], b2, b3);
                MMA_F16(C[nt2][1], A[1][1], b2, b3);
            }
        }
        float* ob = out + (size_t)b * (NTOK * DIM);
        #pragma unroll
        for (int nt2 = 0; nt2 < 2; nt2++) {
            const int j0 = (wid * 2 + nt2) * 8 + qd * 2;
            #pragma unroll
            for (int mt = 0; mt < 2; mt++) {
                const int row = mt * 16 + g;   // <= 23, always in range
                *(float2*)(ob + row * DIM + j0) = make_float2(C[nt2][mt][0], C[nt2][mt][1]);
                if (row + 8 < NTOK)
                    *(float2*)(ob + (row + 8) * DIM + j0) = make_float2(C[nt2][mt][2], C[nt2][mt][3]);
            }
        }
    }
}

extern "C" void kernel_launch(void* const* d_in, const int* in_sizes, int n_in,
                              void* d_out, int out_size)
{
    const float* x          = (const float*)d_in[0];
    const float* mask       = (const float*)d_in[1];
    const int*   ids_keep   = (const int*)  d_in[2];
    const float* qkv_w      = (const float*)d_in[3];
    const float* qkv_b      = (const float*)d_in[4];
    const float* proj_w     = (const float*)d_in[5];
    const float* proj_b     = (const float*)d_in[6];
    const float* bias_table = (const float*)d_in[7];
    const int*   rel_index  = (const int*)  d_in[8];

    const int total = 8192 + NWIN * NH * NTOK * NTOK;
    prologue<<<(total + 255) / 256, 256>>>(qkv_w, proj_w, mask, ids_keep,
                                           bias_table, rel_index);

    const int smem_bytes = SM_FLOATS * 4;
    cudaFuncSetAttribute(win_attn_kernel,
                         cudaFuncAttributeMaxDynamicSharedMemorySize, smem_bytes);
    win_attn_kernel<<<4096, 256, smem_bytes>>>(x, qkv_b, proj_b, (float*)d_out);
}